// round 6
// baseline (speedup 1.0000x reference)
#include <cuda_runtime.h>
#include <cuda_bf16.h>

// NonSparsePLIF: v[t] = where(v[t-1]*d + x[t] >= 1.0, 0, v[t-1]*d + x[t])
// x_seq [T=16, 4194304] f32, decay [1] f32. HBM-bound streaming scan.
// R6: best shape (block=256, grid=4096, __stcs) + 2-timestep batching:
// group loads and stores into pairs to lengthen same-direction DRAM bursts
// (bus-turnaround hypothesis for the ~20% gap to spec BW).

#define T_STEPS 16
#define SPATIAL 4194304            // 16*64*64*64
#define SPATIAL4 (SPATIAL / 4)     // float4 elements per timestep plane
#define THREADS 256
#define VTH 1.0f

__global__ __launch_bounds__(THREADS) void plif_kernel(
    const float4* __restrict__ x,      // [T, SPATIAL4]
    const float* __restrict__ decay,   // [1]
    float4* __restrict__ out)          // [T, SPATIAL4]
{
    const int i = blockIdx.x * THREADS + threadIdx.x;
    if (i >= SPATIAL4) return;

    const float d = decay[0];

    float4 v = make_float4(0.f, 0.f, 0.f, 0.f);

#pragma unroll
    for (int t = 0; t < T_STEPS; t += 2) {
        const size_t idx0 = (size_t)t * SPATIAL4 + i;
        const size_t idx1 = idx0 + SPATIAL4;

        // Both plane loads issued back-to-back (read burst).
        const float4 x0 = x[idx0];
        const float4 x1 = x[idx1];

        // Step t
        float4 v0;
        v0.x = fmaf(v.x, d, x0.x);
        v0.y = fmaf(v.y, d, x0.y);
        v0.z = fmaf(v.z, d, x0.z);
        v0.w = fmaf(v.w, d, x0.w);
        v0.x = (v0.x >= VTH) ? 0.f : v0.x;
        v0.y = (v0.y >= VTH) ? 0.f : v0.y;
        v0.z = (v0.z >= VTH) ? 0.f : v0.z;
        v0.w = (v0.w >= VTH) ? 0.f : v0.w;

        // Step t+1
        float4 v1;
        v1.x = fmaf(v0.x, d, x1.x);
        v1.y = fmaf(v0.y, d, x1.y);
        v1.z = fmaf(v0.z, d, x1.z);
        v1.w = fmaf(v0.w, d, x1.w);
        v1.x = (v1.x >= VTH) ? 0.f : v1.x;
        v1.y = (v1.y >= VTH) ? 0.f : v1.y;
        v1.z = (v1.z >= VTH) ? 0.f : v1.z;
        v1.w = (v1.w >= VTH) ? 0.f : v1.w;

        // Both stores issued back-to-back (write burst).
        __stcs(&out[idx0], v0);
        __stcs(&out[idx1], v1);

        v = v1;
    }
}

extern "C" void kernel_launch(void* const* d_in, const int* in_sizes, int n_in,
                              void* d_out, int out_size)
{
    const float4* x   = (const float4*)d_in[0];
    const float*  dec = (const float*)d_in[1];
    float4*       out = (float4*)d_out;

    const int blocks = (SPATIAL4 + THREADS - 1) / THREADS;  // 4096
    plif_kernel<<<blocks, THREADS>>>(x, dec, out);
}